// round 1
// baseline (speedup 1.0000x reference)
#include <cuda_runtime.h>
#include <cuda_bf16.h>
#include <math.h>

// Problem constants
#define NTOK 4096
#define DIM  512
#define HID  2048
#define NEXP 8

// Scratch (device globals: allocation-free per harness rules)
__device__ float g_H[(size_t)NTOK * NEXP * HID];   // 256 MiB: gelu(x@w1+b1)
__device__ float g_leaf[NTOK * NEXP];              // leaf probabilities

// ---------------------------------------------------------------------------
// Kernel 1: router — one warp per token. 7 dot(512) -> sigmoid -> tree probs.
// ---------------------------------------------------------------------------
__global__ void router_kernel(const float* __restrict__ x,
                              const float* __restrict__ rw,
                              const float* __restrict__ rb) {
    int gwarp = (blockIdx.x * blockDim.x + threadIdx.x) >> 5;
    int lane  = threadIdx.x & 31;
    if (gwarp >= NTOK) return;
    const float* xr = x + (size_t)gwarp * DIM;

    float acc[7];
#pragma unroll
    for (int r = 0; r < 7; r++) acc[r] = 0.f;

    for (int k = lane; k < DIM; k += 32) {
        float xv = xr[k];
#pragma unroll
        for (int r = 0; r < 7; r++) acc[r] = fmaf(xv, rw[r * DIM + k], acc[r]);
    }
#pragma unroll
    for (int r = 0; r < 7; r++) {
#pragma unroll
        for (int o = 16; o > 0; o >>= 1)
            acc[r] += __shfl_xor_sync(0xffffffffu, acc[r], o);
    }

    if (lane < NEXP) {
        float p[7];
#pragma unroll
        for (int r = 0; r < 7; r++)
            p[r] = 1.f / (1.f + expf(-(acc[r] + rb[r])));

        int l = lane;
        int b0 = (l >> 2) & 1, b1 = (l >> 1) & 1, b2 = l & 1;
        // level 0: router 0
        float f0 = b0 ? p[0] : (1.f - p[0]);
        // level 1: router 1 + b0
        float q1 = b0 ? p[2] : p[1];
        float f1 = b1 ? q1 : (1.f - q1);
        // level 2: router 3 + (l>>1)
        int i2 = l >> 1;
        float q2 = (i2 == 0) ? p[3] : (i2 == 1) ? p[4] : (i2 == 2) ? p[5] : p[6];
        float f2 = b2 ? q2 : (1.f - q2);

        g_leaf[gwarp * NEXP + l] = f0 * f1 * f2;
    }
}

// ---------------------------------------------------------------------------
// Kernel 2: GEMM1 + bias + exact GELU.  H[n,e,h] = gelu(X[n,:] @ W1[e][:,h] + b1)
// 64x64 tile, BK=16, 256 threads, 4x4 microtile.
// ---------------------------------------------------------------------------
#define BM 64
#define BN 64
#define BK 16

__global__ __launch_bounds__(256) void gemm1_gelu_kernel(
    const float* __restrict__ X,   // [NTOK, DIM]
    const float* __restrict__ W1,  // [E, DIM, HID]
    const float* __restrict__ b1)  // [E, HID]
{
    __shared__ __align__(16) float As[BK][BM];
    __shared__ __align__(16) float Bs[BK][BN];

    const int e  = blockIdx.z;
    const int nb = blockIdx.y * BM;
    const int cb = blockIdx.x * BN;
    const int tid = threadIdx.x;
    const int tx = tid & 15;
    const int ty = tid >> 4;

    const float* Wp = W1 + (size_t)e * DIM * HID;

    const int arow  = tid >> 2;          // 0..63
    const int acol4 = (tid & 3) * 4;     // 0,4,8,12
    const int brow  = tid >> 4;          // 0..15
    const int bcol4 = (tid & 15) * 4;    // 0..60

    float acc[4][4] = {};

    for (int k0 = 0; k0 < DIM; k0 += BK) {
        float4 av = *(const float4*)(X + (size_t)(nb + arow) * DIM + k0 + acol4);
        As[acol4 + 0][arow] = av.x;
        As[acol4 + 1][arow] = av.y;
        As[acol4 + 2][arow] = av.z;
        As[acol4 + 3][arow] = av.w;
        float4 bv = *(const float4*)(Wp + (size_t)(k0 + brow) * HID + cb + bcol4);
        *(float4*)&Bs[brow][bcol4] = bv;
        __syncthreads();

#pragma unroll
        for (int kk = 0; kk < BK; kk++) {
            float4 a4 = *(const float4*)&As[kk][ty * 4];
            float4 b4 = *(const float4*)&Bs[kk][tx * 4];
            float ar[4] = {a4.x, a4.y, a4.z, a4.w};
            float br[4] = {b4.x, b4.y, b4.z, b4.w};
#pragma unroll
            for (int i = 0; i < 4; i++)
#pragma unroll
                for (int j = 0; j < 4; j++)
                    acc[i][j] = fmaf(ar[i], br[j], acc[i][j]);
        }
        __syncthreads();
    }

    // epilogue: bias + exact gelu, store to g_H
#pragma unroll
    for (int i = 0; i < 4; i++) {
        int n = nb + ty * 4 + i;
        float4 o;
        float* ov = (float*)&o;
#pragma unroll
        for (int j = 0; j < 4; j++) {
            int c = cb + tx * 4 + j;
            float h = acc[i][j] + b1[e * HID + c];
            ov[j] = 0.5f * h * (1.f + erff(h * 0.70710678118654752f));
        }
        *(float4*)(g_H + ((size_t)n * NEXP + e) * HID + cb + tx * 4) = o;
    }
}

// ---------------------------------------------------------------------------
// Kernel 3: GEMM2 over all experts + bias + leaf-weighted combine.
// out[n,d] = sum_e leaf[n,e] * (H[n,e,:] @ W2[e][:,d] + b2[e,d])
// ---------------------------------------------------------------------------
__global__ __launch_bounds__(256) void gemm2_combine_kernel(
    const float* __restrict__ W2,  // [E, HID, DIM]
    const float* __restrict__ b2,  // [E, DIM]
    float* __restrict__ out)       // [NTOK, DIM]
{
    __shared__ __align__(16) float As[BK][BM];
    __shared__ __align__(16) float Bs[BK][BN];

    const int nb = blockIdx.y * BM;
    const int cb = blockIdx.x * BN;
    const int tid = threadIdx.x;
    const int tx = tid & 15;
    const int ty = tid >> 4;

    const int arow  = tid >> 2;
    const int acol4 = (tid & 3) * 4;
    const int brow  = tid >> 4;
    const int bcol4 = (tid & 15) * 4;

    float out_acc[4][4] = {};

    for (int e = 0; e < NEXP; e++) {
        const float* Wp = W2 + (size_t)e * HID * DIM;
        const float* Hp = g_H + ((size_t)(nb + arow) * NEXP + e) * HID;
        float acc[4][4] = {};

        for (int k0 = 0; k0 < HID; k0 += BK) {
            float4 av = *(const float4*)(Hp + k0 + acol4);
            As[acol4 + 0][arow] = av.x;
            As[acol4 + 1][arow] = av.y;
            As[acol4 + 2][arow] = av.z;
            As[acol4 + 3][arow] = av.w;
            float4 bv = *(const float4*)(Wp + (size_t)(k0 + brow) * DIM + cb + bcol4);
            *(float4*)&Bs[brow][bcol4] = bv;
            __syncthreads();

#pragma unroll
            for (int kk = 0; kk < BK; kk++) {
                float4 a4 = *(const float4*)&As[kk][ty * 4];
                float4 b4 = *(const float4*)&Bs[kk][tx * 4];
                float ar[4] = {a4.x, a4.y, a4.z, a4.w};
                float br[4] = {b4.x, b4.y, b4.z, b4.w};
#pragma unroll
                for (int i = 0; i < 4; i++)
#pragma unroll
                    for (int j = 0; j < 4; j++)
                        acc[i][j] = fmaf(ar[i], br[j], acc[i][j]);
            }
            __syncthreads();
        }

        // weighted accumulate
#pragma unroll
        for (int i = 0; i < 4; i++) {
            float lw = g_leaf[(size_t)(nb + ty * 4 + i) * NEXP + e];
#pragma unroll
            for (int j = 0; j < 4; j++) {
                float yv = acc[i][j] + b2[e * DIM + cb + tx * 4 + j];
                out_acc[i][j] = fmaf(lw, yv, out_acc[i][j]);
            }
        }
    }

#pragma unroll
    for (int i = 0; i < 4; i++) {
        int n = nb + ty * 4 + i;
        float4 o;
        float* ov = (float*)&o;
#pragma unroll
        for (int j = 0; j < 4; j++) ov[j] = out_acc[i][j];
        *(float4*)(out + (size_t)n * DIM + cb + tx * 4) = o;
    }
}

// ---------------------------------------------------------------------------
extern "C" void kernel_launch(void* const* d_in, const int* in_sizes, int n_in,
                              void* d_out, int out_size) {
    const float* x  = (const float*)d_in[0];  // [4,1024,512]
    const float* rw = (const float*)d_in[1];  // [7,512]
    const float* rb = (const float*)d_in[2];  // [7]
    const float* w1 = (const float*)d_in[3];  // [8,512,2048]
    const float* b1 = (const float*)d_in[4];  // [8,2048]
    const float* w2 = (const float*)d_in[5];  // [8,2048,512]
    const float* b2 = (const float*)d_in[6];  // [8,512]
    float* out = (float*)d_out;               // [4,1024,512]

    // Router: one warp per token (4096 warps, 8 warps/block)
    router_kernel<<<NTOK / 8, 256>>>(x, rw, rb);

    // GEMM1 + GELU: grid (HID/64, NTOK/64, E)
    dim3 g1(HID / BN, NTOK / BM, NEXP);
    gemm1_gelu_kernel<<<g1, 256>>>(x, w1, b1);

    // GEMM2 + combine: grid (DIM/64, NTOK/64)
    dim3 g2(DIM / BN, NTOK / BM);
    gemm2_combine_kernel<<<g2, 256>>>(w2, b2, out);
}

// round 4
// speedup vs baseline: 3.4884x; 3.4884x over previous
#include <cuda_runtime.h>
#include <cuda_bf16.h>
#include <math.h>
#include <cstdint>

#define NTOK 4096
#define DIM  512
#define HID  2048
#define NEXP 8
#define KTOT (NEXP * HID)   // 16384

// ---------------------------------------------------------------------------
// Device scratch (allocation-free per harness rules)
// ---------------------------------------------------------------------------
__device__ __nv_bfloat16 g_xh[NTOK * DIM];
__device__ __nv_bfloat16 g_xl[NTOK * DIM];
__device__ __nv_bfloat16 g_w1h[NEXP * DIM * HID];
__device__ __nv_bfloat16 g_w1l[NEXP * DIM * HID];
__device__ __nv_bfloat16 g_w2h[KTOT * DIM];
__device__ __nv_bfloat16 g_w2l[KTOT * DIM];
__device__ __nv_bfloat16 g_Hh[(size_t)NTOK * KTOT];
__device__ __nv_bfloat16 g_Hl[(size_t)NTOK * KTOT];
__device__ float g_leaf[NTOK * NEXP];
__device__ float g_b2c[NTOK * DIM];

// ---------------------------------------------------------------------------
// Tiling constants
// ---------------------------------------------------------------------------
#define BM 128
#define BN 128
#define BK 32
#define THREADS 256
#define STAGES 3
#define A_PITCH 40
#define B_PITCH 136
#define ASZB (BM * A_PITCH * 2)
#define BSZB (BK * B_PITCH * 2)
#define STAGEB (2 * ASZB + 2 * BSZB)
#define SMEM_BYTES (STAGES * STAGEB)

// ---------------------------------------------------------------------------
// PTX helpers (portable ISA only)
// ---------------------------------------------------------------------------
__device__ __forceinline__ uint32_t smem_u32(const void* p) {
    uint32_t a;
    asm("{ .reg .u64 t; cvta.to.shared.u64 t, %1; cvt.u32.u64 %0, t; }" : "=r"(a) : "l"(p));
    return a;
}
__device__ __forceinline__ void cp16(uint32_t dst, const void* src) {
    asm volatile("cp.async.cg.shared.global [%0], [%1], 16;" :: "r"(dst), "l"(src));
}
#define CP_COMMIT() asm volatile("cp.async.commit_group;" ::: "memory")
#define CP_WAIT1()  asm volatile("cp.async.wait_group 1;" ::: "memory")

__device__ __forceinline__ void ldsm_x4(uint32_t* r, uint32_t a) {
    asm volatile("ldmatrix.sync.aligned.m8n8.x4.shared.b16 {%0,%1,%2,%3}, [%4];"
                 : "=r"(r[0]), "=r"(r[1]), "=r"(r[2]), "=r"(r[3]) : "r"(a));
}
__device__ __forceinline__ void ldsm_x4t(uint32_t* r, uint32_t a) {
    asm volatile("ldmatrix.sync.aligned.m8n8.x4.trans.shared.b16 {%0,%1,%2,%3}, [%4];"
                 : "=r"(r[0]), "=r"(r[1]), "=r"(r[2]), "=r"(r[3]) : "r"(a));
}
__device__ __forceinline__ void mma16816(float* d, const uint32_t* a, const uint32_t* b) {
    asm volatile(
        "mma.sync.aligned.m16n8k16.row.col.f32.bf16.bf16.f32 "
        "{%0,%1,%2,%3},{%4,%5,%6,%7},{%8,%9},{%0,%1,%2,%3};"
        : "+f"(d[0]), "+f"(d[1]), "+f"(d[2]), "+f"(d[3])
        : "r"(a[0]), "r"(a[1]), "r"(a[2]), "r"(a[3]), "r"(b[0]), "r"(b[1]));
}

__device__ __forceinline__ void split_bf16(float v, __nv_bfloat16& hi, __nv_bfloat16& lo) {
    hi = __float2bfloat16(v);
    lo = __float2bfloat16(v - __bfloat162float(hi));
}
__device__ __forceinline__ float gelu_f(float h) {
    return 0.5f * h * (1.f + erff(h * 0.70710678118654752f));
}

// ---------------------------------------------------------------------------
// GEMM core (same as R3): C[BMxBN] += split3(A)@split3(B), cp.async 3-stage
// ---------------------------------------------------------------------------
template <int LDA, int LDB, int NK>
__device__ __forceinline__ void gemm_core(
    const __nv_bfloat16* __restrict__ gAh, const __nv_bfloat16* __restrict__ gAl,
    const __nv_bfloat16* __restrict__ gBh, const __nv_bfloat16* __restrict__ gBl,
    uint32_t sb, float (*c)[4])
{
    const int tid = threadIdx.x;
    const int lane = tid & 31, wid = tid >> 5;
    const int wm = wid & 1, wn = wid >> 1;
    const int lr = lane & 15, lc = (lane >> 4) * 8;

    auto load_stage = [&](int s, int kt) {
        const int k0 = kt * BK;
        uint32_t aH = sb + s * STAGEB, aL = aH + ASZB;
        uint32_t bH = aH + 2 * ASZB, bL = bH + BSZB;
#pragma unroll
        for (int i = 0; i < 2; i++) {
            int ch = tid + i * THREADS;
            int arow = ch >> 2, aseg = ch & 3;
            uint32_t ad = (uint32_t)(arow * A_PITCH + aseg * 8) * 2;
            cp16(aH + ad, gAh + (size_t)arow * LDA + k0 + aseg * 8);
            cp16(aL + ad, gAl + (size_t)arow * LDA + k0 + aseg * 8);
            int brow = ch >> 4, bseg = ch & 15;
            uint32_t bd = (uint32_t)(brow * B_PITCH + bseg * 8) * 2;
            cp16(bH + bd, gBh + (size_t)(k0 + brow) * LDB + bseg * 8);
            cp16(bL + bd, gBl + (size_t)(k0 + brow) * LDB + bseg * 8);
        }
    };

    load_stage(0, 0); CP_COMMIT();
    load_stage(1, 1); CP_COMMIT();

    for (int kt = 0; kt < NK; kt++) {
        CP_WAIT1();
        __syncthreads();
        if (kt + 2 < NK) load_stage((kt + 2) % STAGES, kt + 2);
        CP_COMMIT();

        const int s = kt % STAGES;
        uint32_t aHb = sb + s * STAGEB, aLb = aHb + ASZB;
        uint32_t bHb = aHb + 2 * ASZB, bLb = bHb + BSZB;

#pragma unroll
        for (int kk = 0; kk < 2; kk++) {
            uint32_t ah[4][4], al[4][4], bh[4][2], bl[4][2];
#pragma unroll
            for (int mi = 0; mi < 4; mi++) {
                uint32_t off = (uint32_t)((wm * 64 + mi * 16 + lr) * A_PITCH + kk * 16 + lc) * 2;
                ldsm_x4(ah[mi], aHb + off);
                ldsm_x4(al[mi], aLb + off);
            }
#pragma unroll
            for (int nj = 0; nj < 2; nj++) {
                uint32_t off = (uint32_t)((kk * 16 + lr) * B_PITCH + wn * 32 + nj * 16 + lc) * 2;
                uint32_t t4[4];
                ldsm_x4t(t4, bHb + off);
                bh[nj * 2][0] = t4[0]; bh[nj * 2][1] = t4[1];
                bh[nj * 2 + 1][0] = t4[2]; bh[nj * 2 + 1][1] = t4[3];
                ldsm_x4t(t4, bLb + off);
                bl[nj * 2][0] = t4[0]; bl[nj * 2][1] = t4[1];
                bl[nj * 2 + 1][0] = t4[2]; bl[nj * 2 + 1][1] = t4[3];
            }
#pragma unroll
            for (int mi = 0; mi < 4; mi++)
#pragma unroll
                for (int ni = 0; ni < 4; ni++) {
                    mma16816(c[mi * 4 + ni], ah[mi], bh[ni]);
                    mma16816(c[mi * 4 + ni], ah[mi], bl[ni]);
                    mma16816(c[mi * 4 + ni], al[mi], bh[ni]);
                }
        }
    }
}

// ---------------------------------------------------------------------------
// GEMM1: H'[t, e*HID+h] = leaf[t,e] * gelu(x @ w1[e] + b1[e]) -> split bf16
// ---------------------------------------------------------------------------
__global__ __launch_bounds__(THREADS) void gemm1_kernel(const float* __restrict__ b1) {
    extern __shared__ char smem[];
    uint32_t sb = smem_u32(smem);
    const int e = blockIdx.z, nb = blockIdx.y * BM, hb = blockIdx.x * BN;

    float c[16][4] = {};
    gemm_core<DIM, HID, DIM / BK>(
        g_xh + (size_t)nb * DIM, g_xl + (size_t)nb * DIM,
        g_w1h + (size_t)e * DIM * HID + hb, g_w1l + (size_t)e * DIM * HID + hb,
        sb, c);

    const int tid = threadIdx.x, lane = tid & 31, wid = tid >> 5;
    const int wm = wid & 1, wn = wid >> 1;

#pragma unroll
    for (int mi = 0; mi < 4; mi++) {
        int r0 = wm * 64 + mi * 16 + (lane >> 2);
        int t0 = nb + r0, t1 = t0 + 8;
        float lw0 = g_leaf[t0 * NEXP + e];
        float lw1 = g_leaf[t1 * NEXP + e];
        size_t base0 = (size_t)t0 * KTOT + (size_t)e * HID + hb;
        size_t base1 = (size_t)t1 * KTOT + (size_t)e * HID + hb;
#pragma unroll
        for (int ni = 0; ni < 4; ni++) {
            int c0 = wn * 32 + ni * 8 + (lane & 3) * 2;
            float ba = b1[e * HID + hb + c0];
            float bb = b1[e * HID + hb + c0 + 1];
            const float* d = c[mi * 4 + ni];
            float v00 = lw0 * gelu_f(d[0] + ba);
            float v01 = lw0 * gelu_f(d[1] + bb);
            float v10 = lw1 * gelu_f(d[2] + ba);
            float v11 = lw1 * gelu_f(d[3] + bb);
            __nv_bfloat162 h2, l2;
            split_bf16(v00, h2.x, l2.x); split_bf16(v01, h2.y, l2.y);
            *(__nv_bfloat162*)(g_Hh + base0 + c0) = h2;
            *(__nv_bfloat162*)(g_Hl + base0 + c0) = l2;
            split_bf16(v10, h2.x, l2.x); split_bf16(v11, h2.y, l2.y);
            *(__nv_bfloat162*)(g_Hh + base1 + c0) = h2;
            *(__nv_bfloat162*)(g_Hl + base1 + c0) = l2;
        }
    }
}

// ---------------------------------------------------------------------------
// GEMM2: out[t,d] = H'[t,:] @ W2cat[:,d] + b2c[t,d]   (K = 16384)
// ---------------------------------------------------------------------------
__global__ __launch_bounds__(THREADS) void gemm2_kernel(float* __restrict__ out) {
    extern __shared__ char smem[];
    uint32_t sb = smem_u32(smem);
    const int nb = blockIdx.y * BM, db = blockIdx.x * BN;

    float c[16][4] = {};
    gemm_core<KTOT, DIM, KTOT / BK>(
        g_Hh + (size_t)nb * KTOT, g_Hl + (size_t)nb * KTOT,
        g_w2h + db, g_w2l + db,
        sb, c);

    const int tid = threadIdx.x, lane = tid & 31, wid = tid >> 5;
    const int wm = wid & 1, wn = wid >> 1;

#pragma unroll
    for (int mi = 0; mi < 4; mi++) {
        int r0 = wm * 64 + mi * 16 + (lane >> 2);
        int t0 = nb + r0, t1 = t0 + 8;
#pragma unroll
        for (int ni = 0; ni < 4; ni++) {
            int c0 = wn * 32 + ni * 8 + (lane & 3) * 2;
            const float* d = c[mi * 4 + ni];
            float2 o0, o1;
            o0.x = d[0] + g_b2c[t0 * DIM + db + c0];
            o0.y = d[1] + g_b2c[t0 * DIM + db + c0 + 1];
            o1.x = d[2] + g_b2c[t1 * DIM + db + c0];
            o1.y = d[3] + g_b2c[t1 * DIM + db + c0 + 1];
            *(float2*)(out + (size_t)t0 * DIM + db + c0) = o0;
            *(float2*)(out + (size_t)t1 * DIM + db + c0) = o1;
        }
    }
}

// ---------------------------------------------------------------------------
// Split kernels — device globals referenced DIRECTLY in device code.
// (Passing __device__ symbols as host-side kernel args silently targets the
//  host shadow via ATS on GB300 — root cause of the R3 failure.)
// ---------------------------------------------------------------------------
__global__ void split_x_kernel(const float* __restrict__ src) {
    int i = blockIdx.x * blockDim.x + threadIdx.x;
    if (i >= NTOK * DIM / 4) return;
    float4 v = ((const float4*)src)[i];
    __nv_bfloat16 h[4], l[4];
    split_bf16(v.x, h[0], l[0]); split_bf16(v.y, h[1], l[1]);
    split_bf16(v.z, h[2], l[2]); split_bf16(v.w, h[3], l[3]);
    *(uint2*)(g_xh + i * 4) = *(uint2*)h;
    *(uint2*)(g_xl + i * 4) = *(uint2*)l;
}
__global__ void split_w1_kernel(const float* __restrict__ src) {
    int i = blockIdx.x * blockDim.x + threadIdx.x;
    if (i >= NEXP * DIM * HID / 4) return;
    float4 v = ((const float4*)src)[i];
    __nv_bfloat16 h[4], l[4];
    split_bf16(v.x, h[0], l[0]); split_bf16(v.y, h[1], l[1]);
    split_bf16(v.z, h[2], l[2]); split_bf16(v.w, h[3], l[3]);
    *(uint2*)(g_w1h + i * 4) = *(uint2*)h;
    *(uint2*)(g_w1l + i * 4) = *(uint2*)l;
}
__global__ void split_w2_kernel(const float* __restrict__ src) {
    int i = blockIdx.x * blockDim.x + threadIdx.x;
    if (i >= KTOT * DIM / 4) return;
    float4 v = ((const float4*)src)[i];
    __nv_bfloat16 h[4], l[4];
    split_bf16(v.x, h[0], l[0]); split_bf16(v.y, h[1], l[1]);
    split_bf16(v.z, h[2], l[2]); split_bf16(v.w, h[3], l[3]);
    *(uint2*)(g_w2h + i * 4) = *(uint2*)h;
    *(uint2*)(g_w2l + i * 4) = *(uint2*)l;
}

__global__ void router_kernel(const float* __restrict__ x,
                              const float* __restrict__ rw,
                              const float* __restrict__ rb) {
    int gwarp = (blockIdx.x * blockDim.x + threadIdx.x) >> 5;
    int lane = threadIdx.x & 31;
    if (gwarp >= NTOK) return;
    const float* xr = x + (size_t)gwarp * DIM;
    float acc[7];
#pragma unroll
    for (int r = 0; r < 7; r++) acc[r] = 0.f;
    for (int k = lane; k < DIM; k += 32) {
        float xv = xr[k];
#pragma unroll
        for (int r = 0; r < 7; r++) acc[r] = fmaf(xv, rw[r * DIM + k], acc[r]);
    }
#pragma unroll
    for (int r = 0; r < 7; r++)
#pragma unroll
        for (int o = 16; o > 0; o >>= 1) acc[r] += __shfl_xor_sync(0xffffffffu, acc[r], o);
    if (lane < NEXP) {
        float p[7];
#pragma unroll
        for (int r = 0; r < 7; r++) p[r] = 1.f / (1.f + expf(-(acc[r] + rb[r])));
        int l = lane;
        int b0 = (l >> 2) & 1, b1i = (l >> 1) & 1, b2i = l & 1;
        float f0 = b0 ? p[0] : (1.f - p[0]);
        float q1 = b0 ? p[2] : p[1];
        float f1 = b1i ? q1 : (1.f - q1);
        int i2 = l >> 1;
        float q2 = (i2 == 0) ? p[3] : (i2 == 1) ? p[4] : (i2 == 2) ? p[5] : p[6];
        float f2 = b2i ? q2 : (1.f - q2);
        g_leaf[gwarp * NEXP + l] = f0 * f1 * f2;
    }
}

__global__ void b2c_kernel(const float* __restrict__ b2) {
    int i = blockIdx.x * blockDim.x + threadIdx.x;
    if (i >= NTOK * DIM) return;
    int t = i >> 9, d = i & (DIM - 1);
    float s = 0.f;
#pragma unroll
    for (int e = 0; e < NEXP; e++) s = fmaf(g_leaf[t * NEXP + e], b2[e * DIM + d], s);
    g_b2c[i] = s;
}

// ---------------------------------------------------------------------------
extern "C" void kernel_launch(void* const* d_in, const int* in_sizes, int n_in,
                              void* d_out, int out_size) {
    const float* x  = (const float*)d_in[0];
    const float* rw = (const float*)d_in[1];
    const float* rb = (const float*)d_in[2];
    const float* w1 = (const float*)d_in[3];
    const float* b1 = (const float*)d_in[4];
    const float* w2 = (const float*)d_in[5];
    const float* b2 = (const float*)d_in[6];
    float* out = (float*)d_out;

    // Sticky attribute; calling unconditionally (no static guards).
    cudaFuncSetAttribute(gemm1_kernel, cudaFuncAttributeMaxDynamicSharedMemorySize, SMEM_BYTES);
    cudaFuncSetAttribute(gemm2_kernel, cudaFuncAttributeMaxDynamicSharedMemorySize, SMEM_BYTES);

    split_x_kernel<<<(NTOK * DIM / 4 + 255) / 256, 256>>>(x);
    split_w1_kernel<<<(NEXP * DIM * HID / 4 + 255) / 256, 256>>>(w1);
    split_w2_kernel<<<(KTOT * DIM / 4 + 255) / 256, 256>>>(w2);
    router_kernel<<<NTOK / 8, 256>>>(x, rw, rb);
    b2c_kernel<<<NTOK * DIM / 256, 256>>>(b2);

    gemm1_kernel<<<dim3(HID / BN, NTOK / BM, NEXP), THREADS, SMEM_BYTES>>>(b1);
    gemm2_kernel<<<dim3(DIM / BN, NTOK / BM), THREADS, SMEM_BYTES>>>(out);
}

// round 5
// speedup vs baseline: 8.2948x; 2.3778x over previous
#include <cuda_runtime.h>
#include <cuda_fp16.h>
#include <math.h>
#include <cstdint>

#define NTOK 4096
#define DIM  512
#define HID  2048
#define NEXP 8
#define KTOT (NEXP * HID)   // 16384

// ---------------------------------------------------------------------------
// Device scratch (allocation-free; referenced ONLY from device code)
// ---------------------------------------------------------------------------
__device__ __half g_xq[NTOK * DIM];
__device__ __half g_w1q[NEXP * DIM * HID];
__device__ __half g_w2q[KTOT * DIM];
__device__ __half g_Hq[(size_t)NTOK * KTOT];
__device__ float g_leaf[NTOK * NEXP];
__device__ float g_b2c[NTOK * DIM];

// ---------------------------------------------------------------------------
// Tiling
// ---------------------------------------------------------------------------
#define BM 128
#define BN 128
#define BK 64
#define THREADS 256
#define STAGES 3
#define A_PITCH 72      // 64 + 8 pad halfs  (144 B rows, conflict-free ldsm)
#define B_PITCH 136     // 128 + 8 pad halfs (272 B rows)
#define ASZB (BM * A_PITCH * 2)     // 18432
#define BSZB (BK * B_PITCH * 2)     // 17408
#define STAGEB (ASZB + BSZB)        // 35840
#define SMEM_BYTES (STAGES * STAGEB) // 107520

// ---------------------------------------------------------------------------
// PTX helpers (portable ISA)
// ---------------------------------------------------------------------------
__device__ __forceinline__ uint32_t smem_u32(const void* p) {
    uint32_t a;
    asm("{ .reg .u64 t; cvta.to.shared.u64 t, %1; cvt.u32.u64 %0, t; }" : "=r"(a) : "l"(p));
    return a;
}
__device__ __forceinline__ void cp16(uint32_t dst, const void* src) {
    asm volatile("cp.async.cg.shared.global [%0], [%1], 16;" :: "r"(dst), "l"(src));
}
#define CP_COMMIT() asm volatile("cp.async.commit_group;" ::: "memory")
#define CP_WAIT1()  asm volatile("cp.async.wait_group 1;" ::: "memory")

__device__ __forceinline__ void ldsm_x4(uint32_t* r, uint32_t a) {
    asm volatile("ldmatrix.sync.aligned.m8n8.x4.shared.b16 {%0,%1,%2,%3}, [%4];"
                 : "=r"(r[0]), "=r"(r[1]), "=r"(r[2]), "=r"(r[3]) : "r"(a));
}
__device__ __forceinline__ void ldsm_x4t(uint32_t* r, uint32_t a) {
    asm volatile("ldmatrix.sync.aligned.m8n8.x4.trans.shared.b16 {%0,%1,%2,%3}, [%4];"
                 : "=r"(r[0]), "=r"(r[1]), "=r"(r[2]), "=r"(r[3]) : "r"(a));
}
__device__ __forceinline__ void mma16816(float* d, const uint32_t* a, const uint32_t* b) {
    asm volatile(
        "mma.sync.aligned.m16n8k16.row.col.f32.f16.f16.f32 "
        "{%0,%1,%2,%3},{%4,%5,%6,%7},{%8,%9},{%0,%1,%2,%3};"
        : "+f"(d[0]), "+f"(d[1]), "+f"(d[2]), "+f"(d[3])
        : "r"(a[0]), "r"(a[1]), "r"(a[2]), "r"(a[3]), "r"(b[0]), "r"(b[1]));
}
__device__ __forceinline__ float gelu_f(float h) {
    return 0.5f * h * (1.f + erff(h * 0.70710678118654752f));
}

// ---------------------------------------------------------------------------
// GEMM core: C[128x128] += A_fp16[128xK] @ B_fp16[KxBN], BK=64, 3-stage cp.async
// 8 warps 2(m) x 4(n), warp tile 64x32, single fp16 product, fp32 accum.
// ---------------------------------------------------------------------------
template <int LDA, int LDB, int NK>
__device__ __forceinline__ void gemm_core(
    const __half* __restrict__ gA, const __half* __restrict__ gB,
    uint32_t sb, float (*c)[4])
{
    const int tid = threadIdx.x;
    const int lane = tid & 31, wid = tid >> 5;
    const int wm = wid & 1, wn = wid >> 1;
    const int lr = lane & 15, lc = (lane >> 4) * 8;

    auto load_stage = [&](int s, int kt) {
        const int k0 = kt * BK;
        uint32_t aB = sb + s * STAGEB;
        uint32_t bB = aB + ASZB;
#pragma unroll
        for (int i = 0; i < 4; i++) {
            int ch = tid + i * THREADS;            // 0..1023
            int arow = ch >> 3, aseg = ch & 7;
            cp16(aB + (uint32_t)(arow * A_PITCH + aseg * 8) * 2,
                 gA + (size_t)arow * LDA + k0 + aseg * 8);
            int brow = ch >> 4, bseg = ch & 15;
            cp16(bB + (uint32_t)(brow * B_PITCH + bseg * 8) * 2,
                 gB + (size_t)(k0 + brow) * LDB + bseg * 8);
        }
    };

    load_stage(0, 0); CP_COMMIT();
    load_stage(1, 1); CP_COMMIT();

    for (int kt = 0; kt < NK; kt++) {
        CP_WAIT1();
        __syncthreads();
        if (kt + 2 < NK) load_stage((kt + 2) % STAGES, kt + 2);
        CP_COMMIT();

        const int s = kt % STAGES;
        uint32_t aB = sb + s * STAGEB;
        uint32_t bB = aB + ASZB;

#pragma unroll
        for (int kk = 0; kk < BK / 16; kk++) {
            uint32_t a4[4][4], b4[4][2];
#pragma unroll
            for (int mi = 0; mi < 4; mi++) {
                uint32_t off = (uint32_t)((wm * 64 + mi * 16 + lr) * A_PITCH + kk * 16 + lc) * 2;
                ldsm_x4(a4[mi], aB + off);
            }
#pragma unroll
            for (int nj = 0; nj < 2; nj++) {
                uint32_t off = (uint32_t)((kk * 16 + lr) * B_PITCH + wn * 32 + nj * 16 + lc) * 2;
                uint32_t t4[4];
                ldsm_x4t(t4, bB + off);
                b4[nj * 2][0] = t4[0]; b4[nj * 2][1] = t4[1];
                b4[nj * 2 + 1][0] = t4[2]; b4[nj * 2 + 1][1] = t4[3];
            }
#pragma unroll
            for (int mi = 0; mi < 4; mi++)
#pragma unroll
                for (int ni = 0; ni < 4; ni++)
                    mma16816(c[mi * 4 + ni], a4[mi], b4[ni]);
        }
    }
}

// ---------------------------------------------------------------------------
// GEMM1: Hq[t, e*HID+h] = fp16( leaf[t,e] * gelu(x @ w1[e] + b1[e]) )
// ---------------------------------------------------------------------------
__global__ __launch_bounds__(THREADS, 2) void gemm1_kernel(const float* __restrict__ b1) {
    extern __shared__ char smem[];
    uint32_t sb = smem_u32(smem);
    const int e = blockIdx.z, nb = blockIdx.y * BM, hb = blockIdx.x * BN;

    float c[16][4] = {};
    gemm_core<DIM, HID, DIM / BK>(
        g_xq + (size_t)nb * DIM, g_w1q + (size_t)e * DIM * HID + hb, sb, c);

    const int tid = threadIdx.x, lane = tid & 31, wid = tid >> 5;
    const int wm = wid & 1, wn = wid >> 1;

#pragma unroll
    for (int mi = 0; mi < 4; mi++) {
        int r0 = wm * 64 + mi * 16 + (lane >> 2);
        int t0 = nb + r0, t1 = t0 + 8;
        float lw0 = g_leaf[t0 * NEXP + e];
        float lw1 = g_leaf[t1 * NEXP + e];
        size_t base0 = (size_t)t0 * KTOT + (size_t)e * HID + hb;
        size_t base1 = (size_t)t1 * KTOT + (size_t)e * HID + hb;
#pragma unroll
        for (int ni = 0; ni < 4; ni++) {
            int c0 = wn * 32 + ni * 8 + (lane & 3) * 2;
            float ba = b1[e * HID + hb + c0];
            float bb = b1[e * HID + hb + c0 + 1];
            const float* d = c[mi * 4 + ni];
            __half2 h0, h1;
            h0.x = __float2half_rn(lw0 * gelu_f(d[0] + ba));
            h0.y = __float2half_rn(lw0 * gelu_f(d[1] + bb));
            h1.x = __float2half_rn(lw1 * gelu_f(d[2] + ba));
            h1.y = __float2half_rn(lw1 * gelu_f(d[3] + bb));
            *(__half2*)(g_Hq + base0 + c0) = h0;
            *(__half2*)(g_Hq + base1 + c0) = h1;
        }
    }
}

// ---------------------------------------------------------------------------
// GEMM2: out[t,d] = Hq[t,:] @ w2q[:,d] + b2c[t,d]   (K = 16384)
// ---------------------------------------------------------------------------
__global__ __launch_bounds__(THREADS, 2) void gemm2_kernel(float* __restrict__ out) {
    extern __shared__ char smem[];
    uint32_t sb = smem_u32(smem);
    const int nb = blockIdx.y * BM, db = blockIdx.x * BN;

    float c[16][4] = {};
    gemm_core<KTOT, DIM, KTOT / BK>(
        g_Hq + (size_t)nb * KTOT, g_w2q + db, sb, c);

    const int tid = threadIdx.x, lane = tid & 31, wid = tid >> 5;
    const int wm = wid & 1, wn = wid >> 1;

#pragma unroll
    for (int mi = 0; mi < 4; mi++) {
        int r0 = wm * 64 + mi * 16 + (lane >> 2);
        int t0 = nb + r0, t1 = t0 + 8;
#pragma unroll
        for (int ni = 0; ni < 4; ni++) {
            int c0 = wn * 32 + ni * 8 + (lane & 3) * 2;
            const float* d = c[mi * 4 + ni];
            float2 o0, o1;
            o0.x = d[0] + g_b2c[t0 * DIM + db + c0];
            o0.y = d[1] + g_b2c[t0 * DIM + db + c0 + 1];
            o1.x = d[2] + g_b2c[t1 * DIM + db + c0];
            o1.y = d[3] + g_b2c[t1 * DIM + db + c0 + 1];
            *(float2*)(out + (size_t)t0 * DIM + db + c0) = o0;
            *(float2*)(out + (size_t)t1 * DIM + db + c0) = o1;
        }
    }
}

// ---------------------------------------------------------------------------
// Converters (device globals referenced directly in device code)
// ---------------------------------------------------------------------------
__global__ void conv_x_kernel(const float* __restrict__ src) {
    int i = blockIdx.x * blockDim.x + threadIdx.x;
    if (i >= NTOK * DIM / 4) return;
    float4 v = ((const float4*)src)[i];
    __half h[4] = {__float2half_rn(v.x), __float2half_rn(v.y),
                   __float2half_rn(v.z), __float2half_rn(v.w)};
    *(uint2*)(g_xq + i * 4) = *(uint2*)h;
}
__global__ void conv_w1_kernel(const float* __restrict__ src) {
    int i = blockIdx.x * blockDim.x + threadIdx.x;
    if (i >= NEXP * DIM * HID / 4) return;
    float4 v = ((const float4*)src)[i];
    __half h[4] = {__float2half_rn(v.x), __float2half_rn(v.y),
                   __float2half_rn(v.z), __float2half_rn(v.w)};
    *(uint2*)(g_w1q + i * 4) = *(uint2*)h;
}
__global__ void conv_w2_kernel(const float* __restrict__ src) {
    int i = blockIdx.x * blockDim.x + threadIdx.x;
    if (i >= KTOT * DIM / 4) return;
    float4 v = ((const float4*)src)[i];
    __half h[4] = {__float2half_rn(v.x), __float2half_rn(v.y),
                   __float2half_rn(v.z), __float2half_rn(v.w)};
    *(uint2*)(g_w2q + i * 4) = *(uint2*)h;
}

__global__ void router_kernel(const float* __restrict__ x,
                              const float* __restrict__ rw,
                              const float* __restrict__ rb) {
    int gwarp = (blockIdx.x * blockDim.x + threadIdx.x) >> 5;
    int lane = threadIdx.x & 31;
    if (gwarp >= NTOK) return;
    const float* xr = x + (size_t)gwarp * DIM;
    float acc[7];
#pragma unroll
    for (int r = 0; r < 7; r++) acc[r] = 0.f;
    for (int k = lane; k < DIM; k += 32) {
        float xv = xr[k];
#pragma unroll
        for (int r = 0; r < 7; r++) acc[r] = fmaf(xv, rw[r * DIM + k], acc[r]);
    }
#pragma unroll
    for (int r = 0; r < 7; r++)
#pragma unroll
        for (int o = 16; o > 0; o >>= 1) acc[r] += __shfl_xor_sync(0xffffffffu, acc[r], o);
    if (lane < NEXP) {
        float p[7];
#pragma unroll
        for (int r = 0; r < 7; r++) p[r] = 1.f / (1.f + expf(-(acc[r] + rb[r])));
        int l = lane;
        int b0 = (l >> 2) & 1, b1i = (l >> 1) & 1, b2i = l & 1;
        float f0 = b0 ? p[0] : (1.f - p[0]);
        float q1 = b0 ? p[2] : p[1];
        float f1 = b1i ? q1 : (1.f - q1);
        int i2 = l >> 1;
        float q2 = (i2 == 0) ? p[3] : (i2 == 1) ? p[4] : (i2 == 2) ? p[5] : p[6];
        float f2 = b2i ? q2 : (1.f - q2);
        g_leaf[gwarp * NEXP + l] = f0 * f1 * f2;
    }
}

__global__ void b2c_kernel(const float* __restrict__ b2) {
    int i = blockIdx.x * blockDim.x + threadIdx.x;
    if (i >= NTOK * DIM) return;
    int t = i >> 9, d = i & (DIM - 1);
    float s = 0.f;
#pragma unroll
    for (int e = 0; e < NEXP; e++) s = fmaf(g_leaf[t * NEXP + e], b2[e * DIM + d], s);
    g_b2c[i] = s;
}

// ---------------------------------------------------------------------------
extern "C" void kernel_launch(void* const* d_in, const int* in_sizes, int n_in,
                              void* d_out, int out_size) {
    const float* x  = (const float*)d_in[0];
    const float* rw = (const float*)d_in[1];
    const float* rb = (const float*)d_in[2];
    const float* w1 = (const float*)d_in[3];
    const float* b1 = (const float*)d_in[4];
    const float* w2 = (const float*)d_in[5];
    const float* b2 = (const float*)d_in[6];
    float* out = (float*)d_out;

    cudaFuncSetAttribute(gemm1_kernel, cudaFuncAttributeMaxDynamicSharedMemorySize, SMEM_BYTES);
    cudaFuncSetAttribute(gemm2_kernel, cudaFuncAttributeMaxDynamicSharedMemorySize, SMEM_BYTES);

    conv_x_kernel<<<(NTOK * DIM / 4 + 255) / 256, 256>>>(x);
    conv_w1_kernel<<<(NEXP * DIM * HID / 4 + 255) / 256, 256>>>(w1);
    conv_w2_kernel<<<(KTOT * DIM / 4 + 255) / 256, 256>>>(w2);
    router_kernel<<<NTOK / 8, 256>>>(x, rw, rb);
    b2c_kernel<<<NTOK * DIM / 256, 256>>>(b2);

    gemm1_kernel<<<dim3(HID / BN, NTOK / BM, NEXP), THREADS, SMEM_BYTES>>>(b1);
    gemm2_kernel<<<dim3(DIM / BN, NTOK / BM), THREADS, SMEM_BYTES>>>(out);
}

// round 6
// speedup vs baseline: 8.9891x; 1.0837x over previous
#include <cuda_runtime.h>
#include <cuda_fp16.h>
#include <math.h>
#include <cstdint>

#define NTOK 4096
#define DIM  512
#define HID  2048
#define NEXP 8
#define KTOT (NEXP * HID)   // 16384
#define KSPLIT 4
#define KCHUNK (KTOT / KSPLIT)  // 4096

// ---------------------------------------------------------------------------
// Device scratch (allocation-free; referenced ONLY from device code)
// ---------------------------------------------------------------------------
__device__ __half g_xq[NTOK * DIM];
__device__ __half g_w1q[NEXP * DIM * HID];
__device__ __half g_w2q[KTOT * DIM];
__device__ __half g_Hq[(size_t)NTOK * KTOT];
__device__ float g_leaf[NTOK * NEXP];
__device__ float g_part[KSPLIT][NTOK * DIM];   // split-K partials (33.5 MB)

// ---------------------------------------------------------------------------
// Tiling
// ---------------------------------------------------------------------------
#define BM 128
#define BN 128
#define BK 64
#define THREADS 256
#define STAGES 3
#define A_PITCH 72
#define B_PITCH 136
#define ASZB (BM * A_PITCH * 2)
#define BSZB (BK * B_PITCH * 2)
#define STAGEB (ASZB + BSZB)
#define SMEM_BYTES (STAGES * STAGEB)   // 107520

// ---------------------------------------------------------------------------
// PTX helpers (portable ISA)
// ---------------------------------------------------------------------------
__device__ __forceinline__ uint32_t smem_u32(const void* p) {
    uint32_t a;
    asm("{ .reg .u64 t; cvta.to.shared.u64 t, %1; cvt.u32.u64 %0, t; }" : "=r"(a) : "l"(p));
    return a;
}
__device__ __forceinline__ void cp16(uint32_t dst, const void* src) {
    asm volatile("cp.async.cg.shared.global [%0], [%1], 16;" :: "r"(dst), "l"(src));
}
#define CP_COMMIT() asm volatile("cp.async.commit_group;" ::: "memory")
#define CP_WAIT1()  asm volatile("cp.async.wait_group 1;" ::: "memory")

__device__ __forceinline__ void ldsm_x4(uint32_t* r, uint32_t a) {
    asm volatile("ldmatrix.sync.aligned.m8n8.x4.shared.b16 {%0,%1,%2,%3}, [%4];"
                 : "=r"(r[0]), "=r"(r[1]), "=r"(r[2]), "=r"(r[3]) : "r"(a));
}
__device__ __forceinline__ void ldsm_x4t(uint32_t* r, uint32_t a) {
    asm volatile("ldmatrix.sync.aligned.m8n8.x4.trans.shared.b16 {%0,%1,%2,%3}, [%4];"
                 : "=r"(r[0]), "=r"(r[1]), "=r"(r[2]), "=r"(r[3]) : "r"(a));
}
__device__ __forceinline__ void mma16816(float* d, const uint32_t* a, const uint32_t* b) {
    asm volatile(
        "mma.sync.aligned.m16n8k16.row.col.f32.f16.f16.f32 "
        "{%0,%1,%2,%3},{%4,%5,%6,%7},{%8,%9},{%0,%1,%2,%3};"
        : "+f"(d[0]), "+f"(d[1]), "+f"(d[2]), "+f"(d[3])
        : "r"(a[0]), "r"(a[1]), "r"(a[2]), "r"(a[3]), "r"(b[0]), "r"(b[1]));
}
__device__ __forceinline__ float gelu_f(float h) {
    return 0.5f * h * (1.f + erff(h * 0.70710678118654752f));
}

// ---------------------------------------------------------------------------
// GEMM core: C[128x128] += A_fp16[128xK] @ B_fp16[KxBN], BK=64, 3-stage cp.async
// ---------------------------------------------------------------------------
template <int LDA, int LDB, int NK>
__device__ __forceinline__ void gemm_core(
    const __half* __restrict__ gA, const __half* __restrict__ gB,
    uint32_t sb, float (*c)[4])
{
    const int tid = threadIdx.x;
    const int lane = tid & 31, wid = tid >> 5;
    const int wm = wid & 1, wn = wid >> 1;
    const int lr = lane & 15, lc = (lane >> 4) * 8;

    auto load_stage = [&](int s, int kt) {
        const int k0 = kt * BK;
        uint32_t aB = sb + s * STAGEB;
        uint32_t bB = aB + ASZB;
#pragma unroll
        for (int i = 0; i < 4; i++) {
            int ch = tid + i * THREADS;
            int arow = ch >> 3, aseg = ch & 7;
            cp16(aB + (uint32_t)(arow * A_PITCH + aseg * 8) * 2,
                 gA + (size_t)arow * LDA + k0 + aseg * 8);
            int brow = ch >> 4, bseg = ch & 15;
            cp16(bB + (uint32_t)(brow * B_PITCH + bseg * 8) * 2,
                 gB + (size_t)(k0 + brow) * LDB + bseg * 8);
        }
    };

    load_stage(0, 0); CP_COMMIT();
    load_stage(1, 1); CP_COMMIT();

    for (int kt = 0; kt < NK; kt++) {
        CP_WAIT1();
        __syncthreads();
        if (kt + 2 < NK) load_stage((kt + 2) % STAGES, kt + 2);
        CP_COMMIT();

        const int s = kt % STAGES;
        uint32_t aB = sb + s * STAGEB;
        uint32_t bB = aB + ASZB;

#pragma unroll
        for (int kk = 0; kk < BK / 16; kk++) {
            uint32_t a4[4][4], b4[4][2];
#pragma unroll
            for (int mi = 0; mi < 4; mi++) {
                uint32_t off = (uint32_t)((wm * 64 + mi * 16 + lr) * A_PITCH + kk * 16 + lc) * 2;
                ldsm_x4(a4[mi], aB + off);
            }
#pragma unroll
            for (int nj = 0; nj < 2; nj++) {
                uint32_t off = (uint32_t)((kk * 16 + lr) * B_PITCH + wn * 32 + nj * 16 + lc) * 2;
                uint32_t t4[4];
                ldsm_x4t(t4, bB + off);
                b4[nj * 2][0] = t4[0]; b4[nj * 2][1] = t4[1];
                b4[nj * 2 + 1][0] = t4[2]; b4[nj * 2 + 1][1] = t4[3];
            }
#pragma unroll
            for (int mi = 0; mi < 4; mi++)
#pragma unroll
                for (int ni = 0; ni < 4; ni++)
                    mma16816(c[mi * 4 + ni], a4[mi], b4[ni]);
        }
    }
}

// ---------------------------------------------------------------------------
// GEMM1: Hq[t, e*HID+h] = fp16( leaf[t,e] * gelu(x @ w1[e] + b1[e]) )
// ---------------------------------------------------------------------------
__global__ __launch_bounds__(THREADS, 2) void gemm1_kernel(const float* __restrict__ b1) {
    extern __shared__ char smem[];
    uint32_t sb = smem_u32(smem);
    const int e = blockIdx.z, nb = blockIdx.y * BM, hb = blockIdx.x * BN;

    float c[16][4] = {};
    gemm_core<DIM, HID, DIM / BK>(
        g_xq + (size_t)nb * DIM, g_w1q + (size_t)e * DIM * HID + hb, sb, c);

    const int tid = threadIdx.x, lane = tid & 31, wid = tid >> 5;
    const int wm = wid & 1, wn = wid >> 1;

#pragma unroll
    for (int mi = 0; mi < 4; mi++) {
        int r0 = wm * 64 + mi * 16 + (lane >> 2);
        int t0 = nb + r0, t1 = t0 + 8;
        float lw0 = g_leaf[t0 * NEXP + e];
        float lw1 = g_leaf[t1 * NEXP + e];
        size_t base0 = (size_t)t0 * KTOT + (size_t)e * HID + hb;
        size_t base1 = (size_t)t1 * KTOT + (size_t)e * HID + hb;
#pragma unroll
        for (int ni = 0; ni < 4; ni++) {
            int c0 = wn * 32 + ni * 8 + (lane & 3) * 2;
            float ba = b1[e * HID + hb + c0];
            float bb = b1[e * HID + hb + c0 + 1];
            const float* d = c[mi * 4 + ni];
            __half2 h0, h1;
            h0.x = __float2half_rn(lw0 * gelu_f(d[0] + ba));
            h0.y = __float2half_rn(lw0 * gelu_f(d[1] + bb));
            h1.x = __float2half_rn(lw1 * gelu_f(d[2] + ba));
            h1.y = __float2half_rn(lw1 * gelu_f(d[3] + bb));
            *(__half2*)(g_Hq + base0 + c0) = h0;
            *(__half2*)(g_Hq + base1 + c0) = h1;
        }
    }
}

// ---------------------------------------------------------------------------
// GEMM2 (split-K): part[z][t,d] = Hq[t, z*4096:(z+1)*4096] @ w2q[z-chunk][:,d]
// grid (DIM/128, NTOK/128, KSPLIT)
// ---------------------------------------------------------------------------
__global__ __launch_bounds__(THREADS, 2) void gemm2_kernel() {
    extern __shared__ char smem[];
    uint32_t sb = smem_u32(smem);
    const int nb = blockIdx.y * BM, db = blockIdx.x * BN, z = blockIdx.z;

    float c[16][4] = {};
    gemm_core<KTOT, DIM, KCHUNK / BK>(
        g_Hq + (size_t)nb * KTOT + (size_t)z * KCHUNK,
        g_w2q + (size_t)z * KCHUNK * DIM + db, sb, c);

    const int tid = threadIdx.x, lane = tid & 31, wid = tid >> 5;
    const int wm = wid & 1, wn = wid >> 1;
    float* pz = g_part[z];

#pragma unroll
    for (int mi = 0; mi < 4; mi++) {
        int r0 = wm * 64 + mi * 16 + (lane >> 2);
        int t0 = nb + r0, t1 = t0 + 8;
#pragma unroll
        for (int ni = 0; ni < 4; ni++) {
            int c0 = wn * 32 + ni * 8 + (lane & 3) * 2;
            const float* d = c[mi * 4 + ni];
            *(float2*)(pz + (size_t)t0 * DIM + db + c0) = make_float2(d[0], d[1]);
            *(float2*)(pz + (size_t)t1 * DIM + db + c0) = make_float2(d[2], d[3]);
        }
    }
}

// ---------------------------------------------------------------------------
// Reduce: out = sum_z part[z] + sum_e leaf*b2   (vectorized float4)
// ---------------------------------------------------------------------------
__global__ void reduce_kernel(const float* __restrict__ b2, float* __restrict__ out) {
    int i = blockIdx.x * blockDim.x + threadIdx.x;     // float4 index
    if (i >= NTOK * DIM / 4) return;
    int t = i >> 7;                 // (i*4)/512
    int dq = i & 127;               // float4 col index within row

    float4 s = ((const float4*)g_part[0])[i];
    float4 p1 = ((const float4*)g_part[1])[i];
    float4 p2 = ((const float4*)g_part[2])[i];
    float4 p3 = ((const float4*)g_part[3])[i];
    s.x += p1.x + p2.x + p3.x;
    s.y += p1.y + p2.y + p3.y;
    s.z += p1.z + p2.z + p3.z;
    s.w += p1.w + p2.w + p3.w;

#pragma unroll
    for (int e = 0; e < NEXP; e++) {
        float lw = g_leaf[t * NEXP + e];
        float4 bv = ((const float4*)b2)[e * 128 + dq];
        s.x = fmaf(lw, bv.x, s.x);
        s.y = fmaf(lw, bv.y, s.y);
        s.z = fmaf(lw, bv.z, s.z);
        s.w = fmaf(lw, bv.w, s.w);
    }
    ((float4*)out)[i] = s;
}

// ---------------------------------------------------------------------------
// Converters + router
// ---------------------------------------------------------------------------
__global__ void conv_x_kernel(const float* __restrict__ src) {
    int i = blockIdx.x * blockDim.x + threadIdx.x;
    if (i >= NTOK * DIM / 4) return;
    float4 v = ((const float4*)src)[i];
    __half h[4] = {__float2half_rn(v.x), __float2half_rn(v.y),
                   __float2half_rn(v.z), __float2half_rn(v.w)};
    *(uint2*)(g_xq + i * 4) = *(uint2*)h;
}
__global__ void conv_w1_kernel(const float* __restrict__ src) {
    int i = blockIdx.x * blockDim.x + threadIdx.x;
    if (i >= NEXP * DIM * HID / 4) return;
    float4 v = ((const float4*)src)[i];
    __half h[4] = {__float2half_rn(v.x), __float2half_rn(v.y),
                   __float2half_rn(v.z), __float2half_rn(v.w)};
    *(uint2*)(g_w1q + i * 4) = *(uint2*)h;
}
__global__ void conv_w2_kernel(const float* __restrict__ src) {
    int i = blockIdx.x * blockDim.x + threadIdx.x;
    if (i >= KTOT * DIM / 4) return;
    float4 v = ((const float4*)src)[i];
    __half h[4] = {__float2half_rn(v.x), __float2half_rn(v.y),
                   __float2half_rn(v.z), __float2half_rn(v.w)};
    *(uint2*)(g_w2q + i * 4) = *(uint2*)h;
}

__global__ void router_kernel(const float* __restrict__ x,
                              const float* __restrict__ rw,
                              const float* __restrict__ rb) {
    int gwarp = (blockIdx.x * blockDim.x + threadIdx.x) >> 5;
    int lane = threadIdx.x & 31;
    if (gwarp >= NTOK) return;
    const float* xr = x + (size_t)gwarp * DIM;
    float acc[7];
#pragma unroll
    for (int r = 0; r < 7; r++) acc[r] = 0.f;
    for (int k = lane; k < DIM; k += 32) {
        float xv = xr[k];
#pragma unroll
        for (int r = 0; r < 7; r++) acc[r] = fmaf(xv, rw[r * DIM + k], acc[r]);
    }
#pragma unroll
    for (int r = 0; r < 7; r++)
#pragma unroll
        for (int o = 16; o > 0; o >>= 1) acc[r] += __shfl_xor_sync(0xffffffffu, acc[r], o);
    if (lane < NEXP) {
        float p[7];
#pragma unroll
        for (int r = 0; r < 7; r++) p[r] = 1.f / (1.f + expf(-(acc[r] + rb[r])));
        int l = lane;
        int b0 = (l >> 2) & 1, b1i = (l >> 1) & 1, b2i = l & 1;
        float f0 = b0 ? p[0] : (1.f - p[0]);
        float q1 = b0 ? p[2] : p[1];
        float f1 = b1i ? q1 : (1.f - q1);
        int i2 = l >> 1;
        float q2 = (i2 == 0) ? p[3] : (i2 == 1) ? p[4] : (i2 == 2) ? p[5] : p[6];
        float f2 = b2i ? q2 : (1.f - q2);
        g_leaf[gwarp * NEXP + l] = f0 * f1 * f2;
    }
}

// ---------------------------------------------------------------------------
extern "C" void kernel_launch(void* const* d_in, const int* in_sizes, int n_in,
                              void* d_out, int out_size) {
    const float* x  = (const float*)d_in[0];
    const float* rw = (const float*)d_in[1];
    const float* rb = (const float*)d_in[2];
    const float* w1 = (const float*)d_in[3];
    const float* b1 = (const float*)d_in[4];
    const float* w2 = (const float*)d_in[5];
    const float* b2 = (const float*)d_in[6];
    float* out = (float*)d_out;

    cudaFuncSetAttribute(gemm1_kernel, cudaFuncAttributeMaxDynamicSharedMemorySize, SMEM_BYTES);
    cudaFuncSetAttribute(gemm2_kernel, cudaFuncAttributeMaxDynamicSharedMemorySize, SMEM_BYTES);

    conv_x_kernel<<<(NTOK * DIM / 4 + 255) / 256, 256>>>(x);
    conv_w1_kernel<<<(NEXP * DIM * HID / 4 + 255) / 256, 256>>>(w1);
    conv_w2_kernel<<<(KTOT * DIM / 4 + 255) / 256, 256>>>(w2);
    router_kernel<<<NTOK / 8, 256>>>(x, rw, rb);

    gemm1_kernel<<<dim3(HID / BN, NTOK / BM, NEXP), THREADS, SMEM_BYTES>>>(b1);
    gemm2_kernel<<<dim3(DIM / BN, NTOK / BM, KSPLIT), THREADS, SMEM_BYTES>>>();
    reduce_kernel<<<(NTOK * DIM / 4 + 255) / 256, 256>>>(b2, out);
}